// round 13
// baseline (speedup 1.0000x reference)
#include <cuda_runtime.h>
#include <cuda_fp16.h>
#include <cstdint>
#include <math.h>

#define Bsz 8
#define Cc  384
#define Np  1024
#define NH  8
#define HD  48
#define SCALE 0.14433756729740643f
#define QSC  0.20824597962350385f   // SCALE * log2(e)

// ------------------ scratch (fp16 hi-only) ------------------
__device__ __align__(16) __half g_xTh[Bsz*Np*Cc];     // [b][n][c]
__device__ __align__(16) __half g_wqh[3*Cc*Cc];        // [o][c]
__device__ __align__(16) __half g_wph[Cc*Cc];          // [o][c]
__device__ __align__(16) __half g_qh[Bsz*NH*Np*HD];    // scaled by QSC
__device__ __align__(16) __half g_kh[Bsz*NH*Np*HD];
__device__ __align__(16) __half g_vh[Bsz*NH*Np*HD];
__device__ __align__(16) __half g_aoh[Bsz*Np*Cc];

// ------------------ helpers ------------------
__device__ __forceinline__ uint32_t smem_u32(const void* p){
  uint32_t a; asm("{ .reg .u64 t; cvta.to.shared.u64 t, %1; cvt.u32.u64 %0, t; }"
                  : "=r"(a) : "l"(p)); return a;
}
__device__ __forceinline__ void ldmx4(uint32_t* r, uint32_t a){
  asm volatile("ldmatrix.sync.aligned.m8n8.x4.shared.b16 {%0,%1,%2,%3}, [%4];"
    : "=r"(r[0]),"=r"(r[1]),"=r"(r[2]),"=r"(r[3]) : "r"(a));
}
__device__ __forceinline__ void ldmx4t(uint32_t* r, uint32_t a){
  asm volatile("ldmatrix.sync.aligned.m8n8.x4.trans.shared.b16 {%0,%1,%2,%3}, [%4];"
    : "=r"(r[0]),"=r"(r[1]),"=r"(r[2]),"=r"(r[3]) : "r"(a));
}
__device__ __forceinline__ void mmahf(float* c, const uint32_t* a, uint32_t b0, uint32_t b1){
  asm volatile("mma.sync.aligned.m16n8k16.row.col.f32.f16.f16.f32 "
    "{%0,%1,%2,%3},{%4,%5,%6,%7},{%8,%9},{%0,%1,%2,%3};"
    : "+f"(c[0]),"+f"(c[1]),"+f"(c[2]),"+f"(c[3])
    : "r"(a[0]),"r"(a[1]),"r"(a[2]),"r"(a[3]),"r"(b0),"r"(b1));
}
__device__ __forceinline__ uint32_t packhf(float x, float y){
  __half2 h = __floats2half2_rn(x, y);
  return *(uint32_t*)&h;
}
__device__ __forceinline__ float ex2(float x){
  float r; asm("ex2.approx.f32 %0, %1;" : "=f"(r) : "f"(x)); return r;
}
__device__ __forceinline__ void cpa16(uint32_t d, const void* s){
  asm volatile("cp.async.cg.shared.global [%0], [%1], 16;" :: "r"(d), "l"(s));
}
#define CP_COMMIT() asm volatile("cp.async.commit_group;" ::: "memory")
#define CP_WAIT0()  asm volatile("cp.async.wait_group 0;" ::: "memory")
#define CP_WAIT1()  asm volatile("cp.async.wait_group 1;" ::: "memory")
__device__ __forceinline__ uint32_t SADDR(uint32_t base, int row, int seg){
  return base + (row << 7) + (((seg ^ (row & 7)) & 7) << 4);
}
__device__ __forceinline__ uint32_t SWADDR(int row, int seg){
  return (row << 7) + (((seg ^ (row & 7)) & 7) << 4);
}

// ------------------ prep kernels ------------------
__global__ __launch_bounds__(256)
void xprep(const float* __restrict__ x, int b0){
  __shared__ float t[32][33];
  const int b = blockIdx.z + b0, n0 = blockIdx.x*32, c0 = blockIdx.y*32;
  const int lx = threadIdx.x & 31, ly = threadIdx.x >> 5;
  const float* xb = x + ((size_t)b*Cc + c0)*Np + n0;
  #pragma unroll
  for (int j = 0; j < 4; ++j)
    t[ly + j*8][lx] = xb[(size_t)(ly + j*8)*Np + lx];
  __syncthreads();
  const int r = threadIdx.x >> 4, cp = threadIdx.x & 15;
  #pragma unroll
  for (int j = 0; j < 2; ++j){
    int rr = r + j*16;
    int idx = ((b*Np + n0 + rr)*Cc + c0 + cp*2);
    *(uint32_t*)(g_xTh + idx) = packhf(t[cp*2][rr], t[cp*2+1][rr]);
  }
}

__global__ __launch_bounds__(256)
void wprep(const float* __restrict__ wq, const float* __restrict__ wp){
  const int i = blockIdx.x*256 + threadIdx.x;
  if (blockIdx.y == 0){
    if (i < 3*Cc*Cc/2){
      float2 v = *(const float2*)(wq + (size_t)i*2);
      ((uint32_t*)g_wqh)[i] = packhf(v.x, v.y);
    }
  } else {
    if (i < Cc*Cc/2){
      float2 v = *(const float2*)(wp + (size_t)i*2);
      ((uint32_t*)g_wph)[i] = packhf(v.x, v.y);
    }
  }
}

// ------------------ GEMM (fp16 single-pass, 2-stage cp.async pipeline) ------------------
template<int MODE>
__global__ __launch_bounds__(256, 2)
void gemm_mma(const float* __restrict__ bias, float* __restrict__ outp, int bofs)
{
  extern __shared__ char sm[];
  const uint32_t sb = smem_u32(sm);
  const int tid = threadIdx.x, wid = tid >> 5, l = tid & 31;
  const int b = blockIdx.z + bofs;
  const int m0blk = blockIdx.y * 128;
  const int nsblk = blockIdx.x * 128;

  const __half *Ah, *Bh;
  if (MODE == 0){
    Ah = g_xTh + (size_t)(b*Np + nsblk)*Cc;
    Bh = g_wqh + (size_t)m0blk*Cc;
  } else {
    Ah = g_wph + (size_t)m0blk*Cc;
    Bh = g_aoh + (size_t)(b*Np + nsblk)*Cc;
  }

  float acc[2][8][4];
  #pragma unroll
  for (int i = 0; i < 2; ++i)
    #pragma unroll
    for (int j = 0; j < 8; ++j)
      #pragma unroll
      for (int e = 0; e < 4; ++e) acc[i][j][e] = 0.f;

  const int m0w = (wid >> 1) * 32;
  const int n0w = (wid & 1) * 64;
  const int arow = (l & 7) + ((l >> 3) & 1) * 8;
  const int aseg = (l >> 4);
  const int brow = (l & 7) + ((l >> 4) << 3);
  const int bseg = (l >> 3) & 1;

  auto load_chunk = [&](int ci, uint32_t st){
    const int k0 = ci * 64;
    #pragma unroll
    for (int i = 0; i < 8; ++i){
      int id = i*256 + tid;
      int buf = id >> 10;
      int rem = id & 1023;
      int row = rem >> 3, seg = rem & 7;
      const __half* base = buf ? Bh : Ah;
      cpa16(sb + st + buf*16384 + SWADDR(row, seg), base + (size_t)row*Cc + k0 + seg*8);
    }
    CP_COMMIT();
  };

  load_chunk(0, 0);

  for (int ci = 0; ci < 6; ++ci){
    const uint32_t st = (ci & 1) * 32768;
    if (ci < 5) load_chunk(ci + 1, ((ci + 1) & 1) * 32768);
    if (ci < 5) { CP_WAIT1(); } else { CP_WAIT0(); }
    __syncthreads();

    #pragma unroll
    for (int kk = 0; kk < 4; ++kk){
      uint32_t ahf[2][4], bfr[4][4];
      #pragma unroll
      for (int mi = 0; mi < 2; ++mi)
        ldmx4(ahf[mi], SADDR(sb + st, m0w + mi*16 + arow, 2*kk + aseg));
      #pragma unroll
      for (int tp = 0; tp < 4; ++tp)
        ldmx4(bfr[tp], SADDR(sb + st + 16384, n0w + tp*16 + brow, 2*kk + bseg));
      #pragma unroll
      for (int tp = 0; tp < 4; ++tp){
        mmahf(acc[0][2*tp  ], ahf[0], bfr[tp][0], bfr[tp][1]);
        mmahf(acc[0][2*tp+1], ahf[0], bfr[tp][2], bfr[tp][3]);
        mmahf(acc[1][2*tp  ], ahf[1], bfr[tp][0], bfr[tp][1]);
        mmahf(acc[1][2*tp+1], ahf[1], bfr[tp][2], bfr[tp][3]);
      }
    }
    __syncthreads();
  }

  const int ddb = (l & 3) * 2;
  if (MODE == 0){
    const int t = m0blk / Cc;
    const float sc = (t == 0) ? QSC : 1.f;
    __half* dst = (t == 0) ? g_qh : (t == 1) ? g_kh : g_vh;
    #pragma unroll
    for (int mi = 0; mi < 2; ++mi){
      const int r0 = nsblk + m0w + mi*16 + (l >> 2);
      #pragma unroll
      for (int j = 0; j < 8; ++j){
        const int o = m0blk + n0w + j*8 + ddb;
        const int rem = o - t*Cc;
        const int hh = rem / HD, dd = rem % HD;
        float2 bv = *(const float2*)(bias + o);
        float v0 = (acc[mi][j][0] + bv.x) * sc;
        float v1 = (acc[mi][j][1] + bv.y) * sc;
        float v2 = (acc[mi][j][2] + bv.x) * sc;
        float v3 = (acc[mi][j][3] + bv.y) * sc;
        const int i0 = ((b*NH + hh)*Np + r0    )*HD + dd;
        const int i1 = ((b*NH + hh)*Np + r0 + 8)*HD + dd;
        *(uint32_t*)(dst + i0) = packhf(v0, v1);
        *(uint32_t*)(dst + i1) = packhf(v2, v3);
      }
    }
  } else {
    #pragma unroll
    for (int mi = 0; mi < 2; ++mi){
      const int or0 = m0blk + m0w + mi*16 + (l >> 2);
      const float b0 = __ldg(bias + or0), b1 = __ldg(bias + or0 + 8);
      #pragma unroll
      for (int j = 0; j < 8; ++j){
        const int nc = nsblk + n0w + j*8 + ddb;
        float2 s0 = make_float2(acc[mi][j][0] + b0, acc[mi][j][1] + b0);
        float2 s1 = make_float2(acc[mi][j][2] + b1, acc[mi][j][3] + b1);
        *(float2*)(outp + ((size_t)b*Cc + or0    )*Np + nc) = s0;
        *(float2*)(outp + ((size_t)b*Cc + or0 + 8)*Np + nc) = s1;
      }
    }
  }
}

// ------------------ attention (16q/warp, ones-MMA row-sum) ------------------
// smem: Qh@0 (16K); stage s @ 16384 + s*32768: Kh@0 Vh@16K  (80KB total)
__global__ __launch_bounds__(256, 2)
void attn_mma(int bh0)
{
  extern __shared__ char sm[];
  const uint32_t sb = smem_u32(sm);
  const int tid = threadIdx.x, wid = tid >> 5, l = tid & 31;
  const int bh = blockIdx.x + bh0;
  const int q0 = blockIdx.y * 128;

  const __half* kbh = g_kh + (size_t)bh*Np*HD;
  const __half* vbh = g_vh + (size_t)bh*Np*HD;

  auto load_kv = [&](int ch, uint32_t st){
    const int ko = ch * 128;
    #pragma unroll
    for (int i = 0; i < 6; ++i){
      int id = i*256 + tid;              // 0..1535
      int region = id >= 768;            // 0:Kh 1:Vh
      int rem = id - region*768;
      int row = rem / 6, seg = rem % 6;
      const __half* src = (region ? vbh : kbh) + (size_t)(ko + row)*HD + seg*8;
      cpa16(sb + st + region*16384 + SWADDR(row, seg), src);
    }
    CP_COMMIT();
  };

  // --- prologue: Q, then chunk-0 ---
  {
    const __half* qsh = g_qh + (size_t)(bh*Np + q0)*HD;
    #pragma unroll
    for (int i = 0; i < 3; ++i){
      int id = i*256 + tid;              // 0..767
      int row = id / 6, seg = id % 6;
      cpa16(sb + SWADDR(row, seg), qsh + row*HD + seg*8);
    }
    CP_COMMIT();
  }
  load_kv(0, 16384);
  CP_WAIT1();              // Q complete
  __syncthreads();

  const int m0w = wid * 16;
  const int arow = (l & 7) + ((l >> 3) & 1) * 8;
  const int aseg = (l >> 4);
  uint32_t qfh[3][4];
  #pragma unroll
  for (int ks = 0; ks < 3; ++ks)
    ldmx4(qfh[ks], SADDR(sb, m0w + arow, 2*ks + aseg));

  float oacc[6][4];
  #pragma unroll
  for (int j = 0; j < 6; ++j)
    #pragma unroll
    for (int e = 0; e < 4; ++e) oacc[j][e] = 0.f;
  float rsacc[4] = {0.f, 0.f, 0.f, 0.f};
  const uint32_t ONES = 0x3C003C00u;

  const int brow = (l & 7) + ((l >> 4) << 3);
  const int bseg = (l >> 3) & 1;
  const int vrow = (l & 7) + ((l >> 3) & 1) * 8;
  const int vsegb = (l >> 4);

  for (int ch = 0; ch < 8; ++ch){
    const uint32_t st = 16384 + (ch & 1) * 32768;
    if (ch < 7) load_kv(ch + 1, 16384 + ((ch + 1) & 1) * 32768);
    if (ch < 7) { CP_WAIT1(); } else { CP_WAIT0(); }
    __syncthreads();

    #pragma unroll
    for (int half = 0; half < 2; ++half){
      float sacc[8][4];
      #pragma unroll
      for (int j = 0; j < 8; ++j)
        #pragma unroll
        for (int e = 0; e < 4; ++e) sacc[j][e] = 0.f;

      #pragma unroll
      for (int ks = 0; ks < 3; ++ks){
        uint32_t bfr[4][4];
        #pragma unroll
        for (int tp = 0; tp < 4; ++tp)
          ldmx4(bfr[tp], SADDR(sb + st, half*64 + tp*16 + brow, 2*ks + bseg));
        #pragma unroll
        for (int tp = 0; tp < 4; ++tp){
          mmahf(sacc[2*tp  ], qfh[ks], bfr[tp][0], bfr[tp][1]);
          mmahf(sacc[2*tp+1], qfh[ks], bfr[tp][2], bfr[tp][3]);
        }
      }

      #pragma unroll
      for (int kt = 0; kt < 4; ++kt){
        float p0 = ex2(sacc[2*kt][0]),   p1 = ex2(sacc[2*kt][1]);
        float p2 = ex2(sacc[2*kt][2]),   p3 = ex2(sacc[2*kt][3]);
        float p4 = ex2(sacc[2*kt+1][0]), p5 = ex2(sacc[2*kt+1][1]);
        float p6 = ex2(sacc[2*kt+1][2]), p7 = ex2(sacc[2*kt+1][3]);
        uint32_t a[4];
        a[0] = packhf(p0, p1);  a[1] = packhf(p2, p3);
        a[2] = packhf(p4, p5);  a[3] = packhf(p6, p7);
        mmahf(rsacc, a, ONES, ONES);
        #pragma unroll
        for (int jp = 0; jp < 3; ++jp){
          uint32_t vh4[4];
          const int vr = half*64 + kt*16 + vrow;
          ldmx4t(vh4, SADDR(sb + st + 16384, vr, 2*jp + vsegb));
          mmahf(oacc[2*jp  ], a, vh4[0], vh4[1]);
          mmahf(oacc[2*jp+1], a, vh4[2], vh4[3]);
        }
      }
    }
    __syncthreads();
  }

  const float inv0 = 1.f / rsacc[0], inv1 = 1.f / rsacc[2];

  const int b = bh >> 3, h = bh & 7;
  const int row0 = q0 + m0w + (l >> 2);
  const int ddb = h*HD + (l & 3)*2;
  #pragma unroll
  for (int jd = 0; jd < 6; ++jd){
    const int i0 = ((b*Np + row0    )*Cc) + ddb + jd*8;
    const int i1 = ((b*Np + row0 + 8)*Cc) + ddb + jd*8;
    *(uint32_t*)(g_aoh + i0) = packhf(oacc[jd][0]*inv0, oacc[jd][1]*inv0);
    *(uint32_t*)(g_aoh + i1) = packhf(oacc[jd][2]*inv1, oacc[jd][3]*inv1);
  }
}

// ------------------ launch: 4-way batch-split pipeline + parallel wprep ------------------
extern "C" void kernel_launch(void* const* d_in, const int* in_sizes, int n_in,
                              void* d_out, int out_size)
{
  const float* x      = (const float*)d_in[0];
  const float* w_qkv  = (const float*)d_in[1];
  const float* b_qkv  = (const float*)d_in[2];
  const float* w_proj = (const float*)d_in[3];
  const float* b_proj = (const float*)d_in[4];
  float* out = (float*)d_out;

  cudaFuncSetAttribute(gemm_mma<0>, cudaFuncAttributeMaxDynamicSharedMemorySize, 65536);
  cudaFuncSetAttribute(gemm_mma<1>, cudaFuncAttributeMaxDynamicSharedMemorySize, 65536);
  cudaFuncSetAttribute(attn_mma,    cudaFuncAttributeMaxDynamicSharedMemorySize, 81920);

  cudaStream_t s2, s3, s4, sW;
  cudaStreamCreateWithFlags(&s2, cudaStreamNonBlocking);
  cudaStreamCreateWithFlags(&s3, cudaStreamNonBlocking);
  cudaStreamCreateWithFlags(&s4, cudaStreamNonBlocking);
  cudaStreamCreateWithFlags(&sW, cudaStreamNonBlocking);
  cudaEvent_t evF, evW, evJ2, evJ3, evJ4;
  cudaEventCreateWithFlags(&evF,  cudaEventDisableTiming);
  cudaEventCreateWithFlags(&evW,  cudaEventDisableTiming);
  cudaEventCreateWithFlags(&evJ2, cudaEventDisableTiming);
  cudaEventCreateWithFlags(&evJ3, cudaEventDisableTiming);
  cudaEventCreateWithFlags(&evJ4, cudaEventDisableTiming);

  // fork from the capture (default) stream
  cudaEventRecord(evF, 0);
  cudaStreamWaitEvent(s2, evF, 0);
  cudaStreamWaitEvent(s3, evF, 0);
  cudaStreamWaitEvent(s4, evF, 0);
  cudaStreamWaitEvent(sW, evF, 0);

  // weight conversion off the critical path
  wprep<<<dim3((3*Cc*Cc/2 + 255)/256, 2), 256, 0, sW>>>(w_qkv, w_proj);
  cudaEventRecord(evW, sW);

  cudaStream_t ws[4] = {(cudaStream_t)0, s2, s3, s4};
  #pragma unroll
  for (int q = 0; q < 4; ++q){
    cudaStream_t s = ws[q];
    const int b0 = q * 2;
    xprep<<<dim3(32, 12, 2), 256, 0, s>>>(x, b0);
    cudaStreamWaitEvent(s, evW, 0);
    gemm_mma<0><<<dim3(8, 9, 2), 256, 65536, s>>>(b_qkv, nullptr, b0);
    attn_mma<<<dim3(16, 8), 256, 81920, s>>>(b0 * NH);
    gemm_mma<1><<<dim3(8, 3, 2), 256, 65536, s>>>(b_proj, out, b0);
  }

  // join all workers back into the default stream
  cudaEventRecord(evJ2, s2);
  cudaEventRecord(evJ3, s3);
  cudaEventRecord(evJ4, s4);
  cudaStreamWaitEvent(0, evJ2, 0);
  cudaStreamWaitEvent(0, evJ3, 0);
  cudaStreamWaitEvent(0, evJ4, 0);

  cudaStreamDestroy(s2); cudaStreamDestroy(s3);
  cudaStreamDestroy(s4); cudaStreamDestroy(sW);
  cudaEventDestroy(evF); cudaEventDestroy(evW);
  cudaEventDestroy(evJ2); cudaEventDestroy(evJ3); cudaEventDestroy(evJ4);
}

// round 14
// speedup vs baseline: 1.0047x; 1.0047x over previous
#include <cuda_runtime.h>
#include <cuda_fp16.h>
#include <cstdint>
#include <math.h>

#define Bsz 8
#define Cc  384
#define Np  1024
#define NH  8
#define HD  48
#define SCALE 0.14433756729740643f
#define QSC  0.20824597962350385f   // SCALE * log2(e)

// ------------------ scratch (fp16 hi-only) ------------------
__device__ __align__(16) __half g_xTh[Bsz*Np*Cc];     // [b][n][c]
__device__ __align__(16) __half g_wqh[3*Cc*Cc];        // [o][c]
__device__ __align__(16) __half g_wph[Cc*Cc];          // [o][c]
__device__ __align__(16) __half g_qh[Bsz*NH*Np*HD];    // scaled by QSC
__device__ __align__(16) __half g_kh[Bsz*NH*Np*HD];
__device__ __align__(16) __half g_vh[Bsz*NH*Np*HD];
__device__ __align__(16) __half g_aoh[Bsz*Np*Cc];

// ------------------ helpers ------------------
__device__ __forceinline__ uint32_t smem_u32(const void* p){
  uint32_t a; asm("{ .reg .u64 t; cvta.to.shared.u64 t, %1; cvt.u32.u64 %0, t; }"
                  : "=r"(a) : "l"(p)); return a;
}
__device__ __forceinline__ void ldmx4(uint32_t* r, uint32_t a){
  asm volatile("ldmatrix.sync.aligned.m8n8.x4.shared.b16 {%0,%1,%2,%3}, [%4];"
    : "=r"(r[0]),"=r"(r[1]),"=r"(r[2]),"=r"(r[3]) : "r"(a));
}
__device__ __forceinline__ void ldmx4t(uint32_t* r, uint32_t a){
  asm volatile("ldmatrix.sync.aligned.m8n8.x4.trans.shared.b16 {%0,%1,%2,%3}, [%4];"
    : "=r"(r[0]),"=r"(r[1]),"=r"(r[2]),"=r"(r[3]) : "r"(a));
}
__device__ __forceinline__ void mmahf(float* c, const uint32_t* a, uint32_t b0, uint32_t b1){
  asm volatile("mma.sync.aligned.m16n8k16.row.col.f32.f16.f16.f32 "
    "{%0,%1,%2,%3},{%4,%5,%6,%7},{%8,%9},{%0,%1,%2,%3};"
    : "+f"(c[0]),"+f"(c[1]),"+f"(c[2]),"+f"(c[3])
    : "r"(a[0]),"r"(a[1]),"r"(a[2]),"r"(a[3]),"r"(b0),"r"(b1));
}
__device__ __forceinline__ uint32_t packhf(float x, float y){
  __half2 h = __floats2half2_rn(x, y);
  return *(uint32_t*)&h;
}
__device__ __forceinline__ float ex2(float x){
  float r; asm("ex2.approx.f32 %0, %1;" : "=f"(r) : "f"(x)); return r;
}
__device__ __forceinline__ void cpa16(uint32_t d, const void* s){
  asm volatile("cp.async.cg.shared.global [%0], [%1], 16;" :: "r"(d), "l"(s));
}
#define CP_COMMIT() asm volatile("cp.async.commit_group;" ::: "memory")
#define CP_WAIT0()  asm volatile("cp.async.wait_group 0;" ::: "memory")
#define CP_WAIT1()  asm volatile("cp.async.wait_group 1;" ::: "memory")
__device__ __forceinline__ uint32_t SADDR(uint32_t base, int row, int seg){
  return base + (row << 7) + (((seg ^ (row & 7)) & 7) << 4);
}
__device__ __forceinline__ uint32_t SWADDR(int row, int seg){
  return (row << 7) + (((seg ^ (row & 7)) & 7) << 4);
}

// ------------------ prep kernels ------------------
__global__ __launch_bounds__(256)
void xprep(const float* __restrict__ x, int b0){
  __shared__ float t[32][33];
  const int b = blockIdx.z + b0, n0 = blockIdx.x*32, c0 = blockIdx.y*32;
  const int lx = threadIdx.x & 31, ly = threadIdx.x >> 5;
  const float* xb = x + ((size_t)b*Cc + c0)*Np + n0;
  #pragma unroll
  for (int j = 0; j < 4; ++j)
    t[ly + j*8][lx] = xb[(size_t)(ly + j*8)*Np + lx];
  __syncthreads();
  const int r = threadIdx.x >> 4, cp = threadIdx.x & 15;
  #pragma unroll
  for (int j = 0; j < 2; ++j){
    int rr = r + j*16;
    int idx = ((b*Np + n0 + rr)*Cc + c0 + cp*2);
    *(uint32_t*)(g_xTh + idx) = packhf(t[cp*2][rr], t[cp*2+1][rr]);
  }
}

__global__ __launch_bounds__(256)
void wprep(const float* __restrict__ wq, const float* __restrict__ wp){
  const int i = blockIdx.x*256 + threadIdx.x;
  if (blockIdx.y == 0){
    if (i < 3*Cc*Cc/2){
      float2 v = *(const float2*)(wq + (size_t)i*2);
      ((uint32_t*)g_wqh)[i] = packhf(v.x, v.y);
    }
  } else {
    if (i < Cc*Cc/2){
      float2 v = *(const float2*)(wp + (size_t)i*2);
      ((uint32_t*)g_wph)[i] = packhf(v.x, v.y);
    }
  }
}

// ------------------ GEMM (fp16 single-pass, 2-stage cp.async pipeline) ------------------
template<int MODE>
__global__ __launch_bounds__(256, 2)
void gemm_mma(const float* __restrict__ bias, float* __restrict__ outp, int bofs)
{
  extern __shared__ char sm[];
  const uint32_t sb = smem_u32(sm);
  const int tid = threadIdx.x, wid = tid >> 5, l = tid & 31;
  const int b = blockIdx.z + bofs;
  const int m0blk = blockIdx.y * 128;
  const int nsblk = blockIdx.x * 128;

  const __half *Ah, *Bh;
  if (MODE == 0){
    Ah = g_xTh + (size_t)(b*Np + nsblk)*Cc;
    Bh = g_wqh + (size_t)m0blk*Cc;
  } else {
    Ah = g_wph + (size_t)m0blk*Cc;
    Bh = g_aoh + (size_t)(b*Np + nsblk)*Cc;
  }

  float acc[2][8][4];
  #pragma unroll
  for (int i = 0; i < 2; ++i)
    #pragma unroll
    for (int j = 0; j < 8; ++j)
      #pragma unroll
      for (int e = 0; e < 4; ++e) acc[i][j][e] = 0.f;

  const int m0w = (wid >> 1) * 32;
  const int n0w = (wid & 1) * 64;
  const int arow = (l & 7) + ((l >> 3) & 1) * 8;
  const int aseg = (l >> 4);
  const int brow = (l & 7) + ((l >> 4) << 3);
  const int bseg = (l >> 3) & 1;

  auto load_chunk = [&](int ci, uint32_t st){
    const int k0 = ci * 64;
    #pragma unroll
    for (int i = 0; i < 8; ++i){
      int id = i*256 + tid;
      int buf = id >> 10;
      int rem = id & 1023;
      int row = rem >> 3, seg = rem & 7;
      const __half* base = buf ? Bh : Ah;
      cpa16(sb + st + buf*16384 + SWADDR(row, seg), base + (size_t)row*Cc + k0 + seg*8);
    }
    CP_COMMIT();
  };

  load_chunk(0, 0);

  for (int ci = 0; ci < 6; ++ci){
    const uint32_t st = (ci & 1) * 32768;
    if (ci < 5) load_chunk(ci + 1, ((ci + 1) & 1) * 32768);
    if (ci < 5) { CP_WAIT1(); } else { CP_WAIT0(); }
    __syncthreads();

    #pragma unroll
    for (int kk = 0; kk < 4; ++kk){
      uint32_t ahf[2][4], bfr[4][4];
      #pragma unroll
      for (int mi = 0; mi < 2; ++mi)
        ldmx4(ahf[mi], SADDR(sb + st, m0w + mi*16 + arow, 2*kk + aseg));
      #pragma unroll
      for (int tp = 0; tp < 4; ++tp)
        ldmx4(bfr[tp], SADDR(sb + st + 16384, n0w + tp*16 + brow, 2*kk + bseg));
      #pragma unroll
      for (int tp = 0; tp < 4; ++tp){
        mmahf(acc[0][2*tp  ], ahf[0], bfr[tp][0], bfr[tp][1]);
        mmahf(acc[0][2*tp+1], ahf[0], bfr[tp][2], bfr[tp][3]);
        mmahf(acc[1][2*tp  ], ahf[1], bfr[tp][0], bfr[tp][1]);
        mmahf(acc[1][2*tp+1], ahf[1], bfr[tp][2], bfr[tp][3]);
      }
    }
    __syncthreads();
  }

  const int ddb = (l & 3) * 2;
  if (MODE == 0){
    const int t = m0blk / Cc;
    const float sc = (t == 0) ? QSC : 1.f;
    __half* dst = (t == 0) ? g_qh : (t == 1) ? g_kh : g_vh;
    #pragma unroll
    for (int mi = 0; mi < 2; ++mi){
      const int r0 = nsblk + m0w + mi*16 + (l >> 2);
      #pragma unroll
      for (int j = 0; j < 8; ++j){
        const int o = m0blk + n0w + j*8 + ddb;
        const int rem = o - t*Cc;
        const int hh = rem / HD, dd = rem % HD;
        float2 bv = *(const float2*)(bias + o);
        float v0 = (acc[mi][j][0] + bv.x) * sc;
        float v1 = (acc[mi][j][1] + bv.y) * sc;
        float v2 = (acc[mi][j][2] + bv.x) * sc;
        float v3 = (acc[mi][j][3] + bv.y) * sc;
        const int i0 = ((b*NH + hh)*Np + r0    )*HD + dd;
        const int i1 = ((b*NH + hh)*Np + r0 + 8)*HD + dd;
        *(uint32_t*)(dst + i0) = packhf(v0, v1);
        *(uint32_t*)(dst + i1) = packhf(v2, v3);
      }
    }
  } else {
    #pragma unroll
    for (int mi = 0; mi < 2; ++mi){
      const int or0 = m0blk + m0w + mi*16 + (l >> 2);
      const float b0 = __ldg(bias + or0), b1 = __ldg(bias + or0 + 8);
      #pragma unroll
      for (int j = 0; j < 8; ++j){
        const int nc = nsblk + n0w + j*8 + ddb;
        float2 s0 = make_float2(acc[mi][j][0] + b0, acc[mi][j][1] + b0);
        float2 s1 = make_float2(acc[mi][j][2] + b1, acc[mi][j][3] + b1);
        *(float2*)(outp + ((size_t)b*Cc + or0    )*Np + nc) = s0;
        *(float2*)(outp + ((size_t)b*Cc + or0 + 8)*Np + nc) = s1;
      }
    }
  }
}

// ------------------ attention (16q/warp, ones-MMA row-sum) ------------------
// smem: Qh@0 (16K); stage s @ 16384 + s*32768: Kh@0 Vh@16K  (80KB total)
__global__ __launch_bounds__(256, 2)
void attn_mma(int bh0)
{
  extern __shared__ char sm[];
  const uint32_t sb = smem_u32(sm);
  const int tid = threadIdx.x, wid = tid >> 5, l = tid & 31;
  const int bh = blockIdx.x + bh0;
  const int q0 = blockIdx.y * 128;

  const __half* kbh = g_kh + (size_t)bh*Np*HD;
  const __half* vbh = g_vh + (size_t)bh*Np*HD;

  auto load_kv = [&](int ch, uint32_t st){
    const int ko = ch * 128;
    #pragma unroll
    for (int i = 0; i < 6; ++i){
      int id = i*256 + tid;              // 0..1535
      int region = id >= 768;            // 0:Kh 1:Vh
      int rem = id - region*768;
      int row = rem / 6, seg = rem % 6;
      const __half* src = (region ? vbh : kbh) + (size_t)(ko + row)*HD + seg*8;
      cpa16(sb + st + region*16384 + SWADDR(row, seg), src);
    }
    CP_COMMIT();
  };

  // --- prologue: Q, then chunk-0 ---
  {
    const __half* qsh = g_qh + (size_t)(bh*Np + q0)*HD;
    #pragma unroll
    for (int i = 0; i < 3; ++i){
      int id = i*256 + tid;              // 0..767
      int row = id / 6, seg = id % 6;
      cpa16(sb + SWADDR(row, seg), qsh + row*HD + seg*8);
    }
    CP_COMMIT();
  }
  load_kv(0, 16384);
  CP_WAIT1();              // Q complete
  __syncthreads();

  const int m0w = wid * 16;
  const int arow = (l & 7) + ((l >> 3) & 1) * 8;
  const int aseg = (l >> 4);
  uint32_t qfh[3][4];
  #pragma unroll
  for (int ks = 0; ks < 3; ++ks)
    ldmx4(qfh[ks], SADDR(sb, m0w + arow, 2*ks + aseg));

  float oacc[6][4];
  #pragma unroll
  for (int j = 0; j < 6; ++j)
    #pragma unroll
    for (int e = 0; e < 4; ++e) oacc[j][e] = 0.f;
  float rsacc[4] = {0.f, 0.f, 0.f, 0.f};
  const uint32_t ONES = 0x3C003C00u;

  const int brow = (l & 7) + ((l >> 4) << 3);
  const int bseg = (l >> 3) & 1;
  const int vrow = (l & 7) + ((l >> 3) & 1) * 8;
  const int vsegb = (l >> 4);

  for (int ch = 0; ch < 8; ++ch){
    const uint32_t st = 16384 + (ch & 1) * 32768;
    if (ch < 7) load_kv(ch + 1, 16384 + ((ch + 1) & 1) * 32768);
    if (ch < 7) { CP_WAIT1(); } else { CP_WAIT0(); }
    __syncthreads();

    #pragma unroll
    for (int half = 0; half < 2; ++half){
      float sacc[8][4];
      #pragma unroll
      for (int j = 0; j < 8; ++j)
        #pragma unroll
        for (int e = 0; e < 4; ++e) sacc[j][e] = 0.f;

      #pragma unroll
      for (int ks = 0; ks < 3; ++ks){
        uint32_t bfr[4][4];
        #pragma unroll
        for (int tp = 0; tp < 4; ++tp)
          ldmx4(bfr[tp], SADDR(sb + st, half*64 + tp*16 + brow, 2*ks + bseg));
        #pragma unroll
        for (int tp = 0; tp < 4; ++tp){
          mmahf(sacc[2*tp  ], qfh[ks], bfr[tp][0], bfr[tp][1]);
          mmahf(sacc[2*tp+1], qfh[ks], bfr[tp][2], bfr[tp][3]);
        }
      }

      #pragma unroll
      for (int kt = 0; kt < 4; ++kt){
        float p0 = ex2(sacc[2*kt][0]),   p1 = ex2(sacc[2*kt][1]);
        float p2 = ex2(sacc[2*kt][2]),   p3 = ex2(sacc[2*kt][3]);
        float p4 = ex2(sacc[2*kt+1][0]), p5 = ex2(sacc[2*kt+1][1]);
        float p6 = ex2(sacc[2*kt+1][2]), p7 = ex2(sacc[2*kt+1][3]);
        uint32_t a[4];
        a[0] = packhf(p0, p1);  a[1] = packhf(p2, p3);
        a[2] = packhf(p4, p5);  a[3] = packhf(p6, p7);
        mmahf(rsacc, a, ONES, ONES);
        #pragma unroll
        for (int jp = 0; jp < 3; ++jp){
          uint32_t vh4[4];
          const int vr = half*64 + kt*16 + vrow;
          ldmx4t(vh4, SADDR(sb + st + 16384, vr, 2*jp + vsegb));
          mmahf(oacc[2*jp  ], a, vh4[0], vh4[1]);
          mmahf(oacc[2*jp+1], a, vh4[2], vh4[3]);
        }
      }
    }
    __syncthreads();
  }

  const float inv0 = 1.f / rsacc[0], inv1 = 1.f / rsacc[2];

  const int b = bh >> 3, h = bh & 7;
  const int row0 = q0 + m0w + (l >> 2);
  const int ddb = h*HD + (l & 3)*2;
  #pragma unroll
  for (int jd = 0; jd < 6; ++jd){
    const int i0 = ((b*Np + row0    )*Cc) + ddb + jd*8;
    const int i1 = ((b*Np + row0 + 8)*Cc) + ddb + jd*8;
    *(uint32_t*)(g_aoh + i0) = packhf(oacc[jd][0]*inv0, oacc[jd][1]*inv0);
    *(uint32_t*)(g_aoh + i1) = packhf(oacc[jd][2]*inv1, oacc[jd][3]*inv1);
  }
}

// ------------------ launch: two-stream batch-split + parallel wprep ------------------
extern "C" void kernel_launch(void* const* d_in, const int* in_sizes, int n_in,
                              void* d_out, int out_size)
{
  const float* x      = (const float*)d_in[0];
  const float* w_qkv  = (const float*)d_in[1];
  const float* b_qkv  = (const float*)d_in[2];
  const float* w_proj = (const float*)d_in[3];
  const float* b_proj = (const float*)d_in[4];
  float* out = (float*)d_out;

  cudaFuncSetAttribute(gemm_mma<0>, cudaFuncAttributeMaxDynamicSharedMemorySize, 65536);
  cudaFuncSetAttribute(gemm_mma<1>, cudaFuncAttributeMaxDynamicSharedMemorySize, 65536);
  cudaFuncSetAttribute(attn_mma,    cudaFuncAttributeMaxDynamicSharedMemorySize, 81920);

  cudaStream_t s2, sW;
  cudaStreamCreateWithFlags(&s2, cudaStreamNonBlocking);
  cudaStreamCreateWithFlags(&sW, cudaStreamNonBlocking);
  cudaEvent_t evF, evW, evJ;
  cudaEventCreateWithFlags(&evF, cudaEventDisableTiming);
  cudaEventCreateWithFlags(&evW, cudaEventDisableTiming);
  cudaEventCreateWithFlags(&evJ, cudaEventDisableTiming);

  // fork from the capture (default) stream
  cudaEventRecord(evF, 0);
  cudaStreamWaitEvent(s2, evF, 0);
  cudaStreamWaitEvent(sW, evF, 0);

  // weight conversion parallel to xprep (gates only the gemms)
  wprep<<<dim3((3*Cc*Cc/2 + 255)/256, 2), 256, 0, sW>>>(w_qkv, w_proj);
  cudaEventRecord(evW, sW);

  // half 1: batches 0-3 on default stream
  xprep<<<dim3(32, 12, 4), 256>>>(x, 0);
  cudaStreamWaitEvent(0, evW, 0);
  gemm_mma<0><<<dim3(8, 9, 4), 256, 65536>>>(b_qkv, nullptr, 0);
  attn_mma<<<dim3(32, 8), 256, 81920>>>(0);
  gemm_mma<1><<<dim3(8, 3, 4), 256, 65536>>>(b_proj, out, 0);

  // half 2: batches 4-7 on s2
  xprep<<<dim3(32, 12, 4), 256, 0, s2>>>(x, 4);
  cudaStreamWaitEvent(s2, evW, 0);
  gemm_mma<0><<<dim3(8, 9, 4), 256, 65536, s2>>>(b_qkv, nullptr, 4);
  attn_mma<<<dim3(32, 8), 256, 81920, s2>>>(32);
  gemm_mma<1><<<dim3(8, 3, 4), 256, 65536, s2>>>(b_proj, out, 4);
  cudaEventRecord(evJ, s2);
  cudaStreamWaitEvent(0, evJ, 0);

  cudaStreamDestroy(s2);
  cudaStreamDestroy(sW);
  cudaEventDestroy(evF);
  cudaEventDestroy(evW);
  cudaEventDestroy(evJ);
}

// round 15
// speedup vs baseline: 1.0359x; 1.0310x over previous
#include <cuda_runtime.h>
#include <cuda_fp16.h>
#include <cstdint>
#include <math.h>

#define Bsz 8
#define Cc  384
#define Np  1024
#define NH  8
#define HD  48
#define SCALE 0.14433756729740643f
#define QSC  0.20824597962350385f   // SCALE * log2(e)

// ------------------ scratch (fp16 hi-only) ------------------
__device__ __align__(16) __half g_xTh[Bsz*Np*Cc];     // [b][n][c]
__device__ __align__(16) __half g_wqh[3*Cc*Cc];        // [o][c]
__device__ __align__(16) __half g_wph[Cc*Cc];          // [o][c]
__device__ __align__(16) __half g_qh[Bsz*NH*Np*HD];    // scaled by QSC
__device__ __align__(16) __half g_kh[Bsz*NH*Np*HD];
__device__ __align__(16) __half g_vh[Bsz*NH*Np*HD];
__device__ __align__(16) __half g_aoh[Bsz*Np*Cc];

// ------------------ helpers ------------------
__device__ __forceinline__ uint32_t smem_u32(const void* p){
  uint32_t a; asm("{ .reg .u64 t; cvta.to.shared.u64 t, %1; cvt.u32.u64 %0, t; }"
                  : "=r"(a) : "l"(p)); return a;
}
__device__ __forceinline__ void ldmx4(uint32_t* r, uint32_t a){
  asm volatile("ldmatrix.sync.aligned.m8n8.x4.shared.b16 {%0,%1,%2,%3}, [%4];"
    : "=r"(r[0]),"=r"(r[1]),"=r"(r[2]),"=r"(r[3]) : "r"(a));
}
__device__ __forceinline__ void ldmx4t(uint32_t* r, uint32_t a){
  asm volatile("ldmatrix.sync.aligned.m8n8.x4.trans.shared.b16 {%0,%1,%2,%3}, [%4];"
    : "=r"(r[0]),"=r"(r[1]),"=r"(r[2]),"=r"(r[3]) : "r"(a));
}
__device__ __forceinline__ void mmahf(float* c, const uint32_t* a, uint32_t b0, uint32_t b1){
  asm volatile("mma.sync.aligned.m16n8k16.row.col.f32.f16.f16.f32 "
    "{%0,%1,%2,%3},{%4,%5,%6,%7},{%8,%9},{%0,%1,%2,%3};"
    : "+f"(c[0]),"+f"(c[1]),"+f"(c[2]),"+f"(c[3])
    : "r"(a[0]),"r"(a[1]),"r"(a[2]),"r"(a[3]),"r"(b0),"r"(b1));
}
__device__ __forceinline__ uint32_t packhf(float x, float y){
  __half2 h = __floats2half2_rn(x, y);
  return *(uint32_t*)&h;
}
__device__ __forceinline__ float ex2(float x){
  float r; asm("ex2.approx.f32 %0, %1;" : "=f"(r) : "f"(x)); return r;
}
__device__ __forceinline__ void cpa16(uint32_t d, const void* s){
  asm volatile("cp.async.cg.shared.global [%0], [%1], 16;" :: "r"(d), "l"(s));
}
#define CP_COMMIT() asm volatile("cp.async.commit_group;" ::: "memory")
#define CP_WAIT0()  asm volatile("cp.async.wait_group 0;" ::: "memory")
#define CP_WAIT1()  asm volatile("cp.async.wait_group 1;" ::: "memory")
__device__ __forceinline__ uint32_t SADDR(uint32_t base, int row, int seg){
  return base + (row << 7) + (((seg ^ (row & 7)) & 7) << 4);
}
__device__ __forceinline__ uint32_t SWADDR(int row, int seg){
  return (row << 7) + (((seg ^ (row & 7)) & 7) << 4);
}

// ------------------ prep kernels ------------------
__global__ __launch_bounds__(256)
void xprep(const float* __restrict__ x, int b0){
  __shared__ float t[32][33];
  const int b = blockIdx.z + b0, n0 = blockIdx.x*32, c0 = blockIdx.y*32;
  const int lx = threadIdx.x & 31, ly = threadIdx.x >> 5;
  const float* xb = x + ((size_t)b*Cc + c0)*Np + n0;
  #pragma unroll
  for (int j = 0; j < 4; ++j)
    t[ly + j*8][lx] = xb[(size_t)(ly + j*8)*Np + lx];
  __syncthreads();
  const int r = threadIdx.x >> 4, cp = threadIdx.x & 15;
  #pragma unroll
  for (int j = 0; j < 2; ++j){
    int rr = r + j*16;
    int idx = ((b*Np + n0 + rr)*Cc + c0 + cp*2);
    *(uint32_t*)(g_xTh + idx) = packhf(t[cp*2][rr], t[cp*2+1][rr]);
  }
}

__global__ __launch_bounds__(256)
void wprep(const float* __restrict__ wq, const float* __restrict__ wp){
  const int i = blockIdx.x*256 + threadIdx.x;
  if (blockIdx.y == 0){
    if (i < 3*Cc*Cc/2){
      float2 v = *(const float2*)(wq + (size_t)i*2);
      ((uint32_t*)g_wqh)[i] = packhf(v.x, v.y);
    }
  } else {
    if (i < Cc*Cc/2){
      float2 v = *(const float2*)(wp + (size_t)i*2);
      ((uint32_t*)g_wph)[i] = packhf(v.x, v.y);
    }
  }
}

// ------------------ GEMM (fp16 single-pass, 2-stage cp.async pipeline) ------------------
template<int MODE>
__global__ __launch_bounds__(256, 2)
void gemm_mma(const float* __restrict__ bias, float* __restrict__ outp, int bofs)
{
  extern __shared__ char sm[];
  const uint32_t sb = smem_u32(sm);
  const int tid = threadIdx.x, wid = tid >> 5, l = tid & 31;
  const int b = blockIdx.z + bofs;
  const int m0blk = blockIdx.y * 128;
  const int nsblk = blockIdx.x * 128;

  const __half *Ah, *Bh;
  if (MODE == 0){
    Ah = g_xTh + (size_t)(b*Np + nsblk)*Cc;
    Bh = g_wqh + (size_t)m0blk*Cc;
  } else {
    Ah = g_wph + (size_t)m0blk*Cc;
    Bh = g_aoh + (size_t)(b*Np + nsblk)*Cc;
  }

  float acc[2][8][4];
  #pragma unroll
  for (int i = 0; i < 2; ++i)
    #pragma unroll
    for (int j = 0; j < 8; ++j)
      #pragma unroll
      for (int e = 0; e < 4; ++e) acc[i][j][e] = 0.f;

  const int m0w = (wid >> 1) * 32;
  const int n0w = (wid & 1) * 64;
  const int arow = (l & 7) + ((l >> 3) & 1) * 8;
  const int aseg = (l >> 4);
  const int brow = (l & 7) + ((l >> 4) << 3);
  const int bseg = (l >> 3) & 1;

  auto load_chunk = [&](int ci, uint32_t st){
    const int k0 = ci * 64;
    #pragma unroll
    for (int i = 0; i < 8; ++i){
      int id = i*256 + tid;
      int buf = id >> 10;
      int rem = id & 1023;
      int row = rem >> 3, seg = rem & 7;
      const __half* base = buf ? Bh : Ah;
      cpa16(sb + st + buf*16384 + SWADDR(row, seg), base + (size_t)row*Cc + k0 + seg*8);
    }
    CP_COMMIT();
  };

  load_chunk(0, 0);

  for (int ci = 0; ci < 6; ++ci){
    const uint32_t st = (ci & 1) * 32768;
    if (ci < 5) load_chunk(ci + 1, ((ci + 1) & 1) * 32768);
    if (ci < 5) { CP_WAIT1(); } else { CP_WAIT0(); }
    __syncthreads();

    #pragma unroll
    for (int kk = 0; kk < 4; ++kk){
      uint32_t ahf[2][4], bfr[4][4];
      #pragma unroll
      for (int mi = 0; mi < 2; ++mi)
        ldmx4(ahf[mi], SADDR(sb + st, m0w + mi*16 + arow, 2*kk + aseg));
      #pragma unroll
      for (int tp = 0; tp < 4; ++tp)
        ldmx4(bfr[tp], SADDR(sb + st + 16384, n0w + tp*16 + brow, 2*kk + bseg));
      #pragma unroll
      for (int tp = 0; tp < 4; ++tp){
        mmahf(acc[0][2*tp  ], ahf[0], bfr[tp][0], bfr[tp][1]);
        mmahf(acc[0][2*tp+1], ahf[0], bfr[tp][2], bfr[tp][3]);
        mmahf(acc[1][2*tp  ], ahf[1], bfr[tp][0], bfr[tp][1]);
        mmahf(acc[1][2*tp+1], ahf[1], bfr[tp][2], bfr[tp][3]);
      }
    }
    __syncthreads();
  }

  const int ddb = (l & 3) * 2;
  if (MODE == 0){
    const int t = m0blk / Cc;
    const float sc = (t == 0) ? QSC : 1.f;
    __half* dst = (t == 0) ? g_qh : (t == 1) ? g_kh : g_vh;
    #pragma unroll
    for (int mi = 0; mi < 2; ++mi){
      const int r0 = nsblk + m0w + mi*16 + (l >> 2);
      #pragma unroll
      for (int j = 0; j < 8; ++j){
        const int o = m0blk + n0w + j*8 + ddb;
        const int rem = o - t*Cc;
        const int hh = rem / HD, dd = rem % HD;
        float2 bv = *(const float2*)(bias + o);
        float v0 = (acc[mi][j][0] + bv.x) * sc;
        float v1 = (acc[mi][j][1] + bv.y) * sc;
        float v2 = (acc[mi][j][2] + bv.x) * sc;
        float v3 = (acc[mi][j][3] + bv.y) * sc;
        const int i0 = ((b*NH + hh)*Np + r0    )*HD + dd;
        const int i1 = ((b*NH + hh)*Np + r0 + 8)*HD + dd;
        *(uint32_t*)(dst + i0) = packhf(v0, v1);
        *(uint32_t*)(dst + i1) = packhf(v2, v3);
      }
    }
  } else {
    #pragma unroll
    for (int mi = 0; mi < 2; ++mi){
      const int or0 = m0blk + m0w + mi*16 + (l >> 2);
      const float b0 = __ldg(bias + or0), b1 = __ldg(bias + or0 + 8);
      #pragma unroll
      for (int j = 0; j < 8; ++j){
        const int nc = nsblk + n0w + j*8 + ddb;
        float2 s0 = make_float2(acc[mi][j][0] + b0, acc[mi][j][1] + b0);
        float2 s1 = make_float2(acc[mi][j][2] + b1, acc[mi][j][3] + b1);
        *(float2*)(outp + ((size_t)b*Cc + or0    )*Np + nc) = s0;
        *(float2*)(outp + ((size_t)b*Cc + or0 + 8)*Np + nc) = s1;
      }
    }
  }
}

// ------------------ attention (16q/warp, ones-MMA row-sum) ------------------
// smem: Qh@0 (16K); stage s @ 16384 + s*32768: Kh@0 Vh@16K  (80KB total)
__global__ __launch_bounds__(256, 2)
void attn_mma(int bh0)
{
  extern __shared__ char sm[];
  const uint32_t sb = smem_u32(sm);
  const int tid = threadIdx.x, wid = tid >> 5, l = tid & 31;
  const int bh = blockIdx.x + bh0;
  const int q0 = blockIdx.y * 128;

  const __half* kbh = g_kh + (size_t)bh*Np*HD;
  const __half* vbh = g_vh + (size_t)bh*Np*HD;

  auto load_kv = [&](int ch, uint32_t st){
    const int ko = ch * 128;
    #pragma unroll
    for (int i = 0; i < 6; ++i){
      int id = i*256 + tid;              // 0..1535
      int region = id >= 768;            // 0:Kh 1:Vh
      int rem = id - region*768;
      int row = rem / 6, seg = rem % 6;
      const __half* src = (region ? vbh : kbh) + (size_t)(ko + row)*HD + seg*8;
      cpa16(sb + st + region*16384 + SWADDR(row, seg), src);
    }
    CP_COMMIT();
  };

  // --- prologue: Q, then chunk-0 ---
  {
    const __half* qsh = g_qh + (size_t)(bh*Np + q0)*HD;
    #pragma unroll
    for (int i = 0; i < 3; ++i){
      int id = i*256 + tid;              // 0..767
      int row = id / 6, seg = id % 6;
      cpa16(sb + SWADDR(row, seg), qsh + row*HD + seg*8);
    }
    CP_COMMIT();
  }
  load_kv(0, 16384);
  CP_WAIT1();              // Q complete
  __syncthreads();

  const int m0w = wid * 16;
  const int arow = (l & 7) + ((l >> 3) & 1) * 8;
  const int aseg = (l >> 4);
  uint32_t qfh[3][4];
  #pragma unroll
  for (int ks = 0; ks < 3; ++ks)
    ldmx4(qfh[ks], SADDR(sb, m0w + arow, 2*ks + aseg));

  float oacc[6][4];
  #pragma unroll
  for (int j = 0; j < 6; ++j)
    #pragma unroll
    for (int e = 0; e < 4; ++e) oacc[j][e] = 0.f;
  float rsacc[4] = {0.f, 0.f, 0.f, 0.f};
  const uint32_t ONES = 0x3C003C00u;

  const int brow = (l & 7) + ((l >> 4) << 3);
  const int bseg = (l >> 3) & 1;
  const int vrow = (l & 7) + ((l >> 3) & 1) * 8;
  const int vsegb = (l >> 4);

  for (int ch = 0; ch < 8; ++ch){
    const uint32_t st = 16384 + (ch & 1) * 32768;
    if (ch < 7) load_kv(ch + 1, 16384 + ((ch + 1) & 1) * 32768);
    if (ch < 7) { CP_WAIT1(); } else { CP_WAIT0(); }
    __syncthreads();

    #pragma unroll
    for (int half = 0; half < 2; ++half){
      float sacc[8][4];
      #pragma unroll
      for (int j = 0; j < 8; ++j)
        #pragma unroll
        for (int e = 0; e < 4; ++e) sacc[j][e] = 0.f;

      #pragma unroll
      for (int ks = 0; ks < 3; ++ks){
        uint32_t bfr[4][4];
        #pragma unroll
        for (int tp = 0; tp < 4; ++tp)
          ldmx4(bfr[tp], SADDR(sb + st, half*64 + tp*16 + brow, 2*ks + bseg));
        #pragma unroll
        for (int tp = 0; tp < 4; ++tp){
          mmahf(sacc[2*tp  ], qfh[ks], bfr[tp][0], bfr[tp][1]);
          mmahf(sacc[2*tp+1], qfh[ks], bfr[tp][2], bfr[tp][3]);
        }
      }

      #pragma unroll
      for (int kt = 0; kt < 4; ++kt){
        float p0 = ex2(sacc[2*kt][0]),   p1 = ex2(sacc[2*kt][1]);
        float p2 = ex2(sacc[2*kt][2]),   p3 = ex2(sacc[2*kt][3]);
        float p4 = ex2(sacc[2*kt+1][0]), p5 = ex2(sacc[2*kt+1][1]);
        float p6 = ex2(sacc[2*kt+1][2]), p7 = ex2(sacc[2*kt+1][3]);
        uint32_t a[4];
        a[0] = packhf(p0, p1);  a[1] = packhf(p2, p3);
        a[2] = packhf(p4, p5);  a[3] = packhf(p6, p7);
        mmahf(rsacc, a, ONES, ONES);
        #pragma unroll
        for (int jp = 0; jp < 3; ++jp){
          uint32_t vh4[4];
          const int vr = half*64 + kt*16 + vrow;
          ldmx4t(vh4, SADDR(sb + st + 16384, vr, 2*jp + vsegb));
          mmahf(oacc[2*jp  ], a, vh4[0], vh4[1]);
          mmahf(oacc[2*jp+1], a, vh4[2], vh4[3]);
        }
      }
    }
    __syncthreads();
  }

  const float inv0 = 1.f / rsacc[0], inv1 = 1.f / rsacc[2];

  const int b = bh >> 3, h = bh & 7;
  const int row0 = q0 + m0w + (l >> 2);
  const int ddb = h*HD + (l & 3)*2;
  #pragma unroll
  for (int jd = 0; jd < 6; ++jd){
    const int i0 = ((b*Np + row0    )*Cc) + ddb + jd*8;
    const int i1 = ((b*Np + row0 + 8)*Cc) + ddb + jd*8;
    *(uint32_t*)(g_aoh + i0) = packhf(oacc[jd][0]*inv0, oacc[jd][1]*inv0);
    *(uint32_t*)(g_aoh + i1) = packhf(oacc[jd][2]*inv1, oacc[jd][3]*inv1);
  }
}

// ------------------ launch: two-stream batch-split pipeline (R12 champion) ------------------
extern "C" void kernel_launch(void* const* d_in, const int* in_sizes, int n_in,
                              void* d_out, int out_size)
{
  const float* x      = (const float*)d_in[0];
  const float* w_qkv  = (const float*)d_in[1];
  const float* b_qkv  = (const float*)d_in[2];
  const float* w_proj = (const float*)d_in[3];
  const float* b_proj = (const float*)d_in[4];
  float* out = (float*)d_out;

  cudaFuncSetAttribute(gemm_mma<0>, cudaFuncAttributeMaxDynamicSharedMemorySize, 65536);
  cudaFuncSetAttribute(gemm_mma<1>, cudaFuncAttributeMaxDynamicSharedMemorySize, 65536);
  cudaFuncSetAttribute(attn_mma,    cudaFuncAttributeMaxDynamicSharedMemorySize, 81920);

  // second stream + fork/join events
  cudaStream_t s2;
  cudaStreamCreateWithFlags(&s2, cudaStreamNonBlocking);
  cudaEvent_t evF, evJ;
  cudaEventCreateWithFlags(&evF, cudaEventDisableTiming);
  cudaEventCreateWithFlags(&evJ, cudaEventDisableTiming);

  // shared prologue on the capture (default) stream
  wprep<<<dim3((3*Cc*Cc/2 + 255)/256, 2), 256>>>(w_qkv, w_proj);
  cudaEventRecord(evF, 0);
  cudaStreamWaitEvent(s2, evF, 0);

  // half 1: batches 0-3 on default stream
  xprep<<<dim3(32, 12, 4), 256>>>(x, 0);
  gemm_mma<0><<<dim3(8, 9, 4), 256, 65536>>>(b_qkv, nullptr, 0);
  attn_mma<<<dim3(32, 8), 256, 81920>>>(0);
  gemm_mma<1><<<dim3(8, 3, 4), 256, 65536>>>(b_proj, out, 0);

  // half 2: batches 4-7 on s2
  xprep<<<dim3(32, 12, 4), 256, 0, s2>>>(x, 4);
  gemm_mma<0><<<dim3(8, 9, 4), 256, 65536, s2>>>(b_qkv, nullptr, 4);
  attn_mma<<<dim3(32, 8), 256, 81920, s2>>>(32);
  gemm_mma<1><<<dim3(8, 3, 4), 256, 65536, s2>>>(b_proj, out, 4);
  cudaEventRecord(evJ, s2);
  cudaStreamWaitEvent(0, evJ, 0);

  cudaStreamDestroy(s2);
  cudaEventDestroy(evF);
  cudaEventDestroy(evJ);
}

// round 16
// speedup vs baseline: 1.0439x; 1.0078x over previous
#include <cuda_runtime.h>
#include <cuda_fp16.h>
#include <cstdint>
#include <math.h>

#define Bsz 8
#define Cc  384
#define Np  1024
#define NH  8
#define HD  48
#define SCALE 0.14433756729740643f
#define QSC  0.20824597962350385f   // SCALE * log2(e)

// ------------------ scratch (fp16 hi-only) ------------------
__device__ __align__(16) __half g_xTh[Bsz*Np*Cc];     // [b][n][c]
__device__ __align__(16) __half g_wqh[3*Cc*Cc];        // [o][c]
__device__ __align__(16) __half g_wph[Cc*Cc];          // [o][c]
__device__ __align__(16) __half g_qh[Bsz*NH*Np*HD];    // scaled by QSC
__device__ __align__(16) __half g_kh[Bsz*NH*Np*HD];
__device__ __align__(16) __half g_vh[Bsz*NH*Np*HD];
__device__ __align__(16) __half g_aoh[Bsz*Np*Cc];

// ------------------ helpers ------------------
__device__ __forceinline__ uint32_t smem_u32(const void* p){
  uint32_t a; asm("{ .reg .u64 t; cvta.to.shared.u64 t, %1; cvt.u32.u64 %0, t; }"
                  : "=r"(a) : "l"(p)); return a;
}
__device__ __forceinline__ void ldmx4(uint32_t* r, uint32_t a){
  asm volatile("ldmatrix.sync.aligned.m8n8.x4.shared.b16 {%0,%1,%2,%3}, [%4];"
    : "=r"(r[0]),"=r"(r[1]),"=r"(r[2]),"=r"(r[3]) : "r"(a));
}
__device__ __forceinline__ void ldmx4t(uint32_t* r, uint32_t a){
  asm volatile("ldmatrix.sync.aligned.m8n8.x4.trans.shared.b16 {%0,%1,%2,%3}, [%4];"
    : "=r"(r[0]),"=r"(r[1]),"=r"(r[2]),"=r"(r[3]) : "r"(a));
}
__device__ __forceinline__ void mmahf(float* c, const uint32_t* a, uint32_t b0, uint32_t b1){
  asm volatile("mma.sync.aligned.m16n8k16.row.col.f32.f16.f16.f32 "
    "{%0,%1,%2,%3},{%4,%5,%6,%7},{%8,%9},{%0,%1,%2,%3};"
    : "+f"(c[0]),"+f"(c[1]),"+f"(c[2]),"+f"(c[3])
    : "r"(a[0]),"r"(a[1]),"r"(a[2]),"r"(a[3]),"r"(b0),"r"(b1));
}
__device__ __forceinline__ uint32_t packhf(float x, float y){
  __half2 h = __floats2half2_rn(x, y);
  return *(uint32_t*)&h;
}
__device__ __forceinline__ float ex2(float x){
  float r; asm("ex2.approx.f32 %0, %1;" : "=f"(r) : "f"(x)); return r;
}
__device__ __forceinline__ void cpa16(uint32_t d, const void* s){
  asm volatile("cp.async.cg.shared.global [%0], [%1], 16;" :: "r"(d), "l"(s));
}
#define CP_COMMIT() asm volatile("cp.async.commit_group;" ::: "memory")
#define CP_WAIT0()  asm volatile("cp.async.wait_group 0;" ::: "memory")
#define CP_WAIT1()  asm volatile("cp.async.wait_group 1;" ::: "memory")
__device__ __forceinline__ uint32_t SADDR(uint32_t base, int row, int seg){
  return base + (row << 7) + (((seg ^ (row & 7)) & 7) << 4);
}
__device__ __forceinline__ uint32_t SWADDR(int row, int seg){
  return (row << 7) + (((seg ^ (row & 7)) & 7) << 4);
}

// ------------------ prep kernels ------------------
__global__ __launch_bounds__(256)
void xprep(const float* __restrict__ x, int b0){
  __shared__ float t[32][33];
  const int b = blockIdx.z + b0, n0 = blockIdx.x*32, c0 = blockIdx.y*32;
  const int lx = threadIdx.x & 31, ly = threadIdx.x >> 5;
  const float* xb = x + ((size_t)b*Cc + c0)*Np + n0;
  #pragma unroll
  for (int j = 0; j < 4; ++j)
    t[ly + j*8][lx] = xb[(size_t)(ly + j*8)*Np + lx];
  __syncthreads();
  const int r = threadIdx.x >> 4, cp = threadIdx.x & 15;
  #pragma unroll
  for (int j = 0; j < 2; ++j){
    int rr = r + j*16;
    int idx = ((b*Np + n0 + rr)*Cc + c0 + cp*2);
    *(uint32_t*)(g_xTh + idx) = packhf(t[cp*2][rr], t[cp*2+1][rr]);
  }
}

__global__ __launch_bounds__(256)
void wprep(const float* __restrict__ wq, const float* __restrict__ wp){
  const int i = blockIdx.x*256 + threadIdx.x;
  if (blockIdx.y == 0){
    if (i < 3*Cc*Cc/2){
      float2 v = *(const float2*)(wq + (size_t)i*2);
      ((uint32_t*)g_wqh)[i] = packhf(v.x, v.y);
    }
  } else {
    if (i < Cc*Cc/2){
      float2 v = *(const float2*)(wp + (size_t)i*2);
      ((uint32_t*)g_wph)[i] = packhf(v.x, v.y);
    }
  }
}

// ------------------ GEMM (fp16 single-pass, 2-stage cp.async pipeline) ------------------
template<int MODE>
__global__ __launch_bounds__(256, 2)
void gemm_mma(const float* __restrict__ bias, float* __restrict__ outp, int bofs)
{
  extern __shared__ char sm[];
  const uint32_t sb = smem_u32(sm);
  const int tid = threadIdx.x, wid = tid >> 5, l = tid & 31;
  const int b = blockIdx.z + bofs;
  const int m0blk = blockIdx.y * 128;
  const int nsblk = blockIdx.x * 128;

  const __half *Ah, *Bh;
  if (MODE == 0){
    Ah = g_xTh + (size_t)(b*Np + nsblk)*Cc;
    Bh = g_wqh + (size_t)m0blk*Cc;
  } else {
    Ah = g_wph + (size_t)m0blk*Cc;
    Bh = g_aoh + (size_t)(b*Np + nsblk)*Cc;
  }

  float acc[2][8][4];
  #pragma unroll
  for (int i = 0; i < 2; ++i)
    #pragma unroll
    for (int j = 0; j < 8; ++j)
      #pragma unroll
      for (int e = 0; e < 4; ++e) acc[i][j][e] = 0.f;

  const int m0w = (wid >> 1) * 32;
  const int n0w = (wid & 1) * 64;
  const int arow = (l & 7) + ((l >> 3) & 1) * 8;
  const int aseg = (l >> 4);
  const int brow = (l & 7) + ((l >> 4) << 3);
  const int bseg = (l >> 3) & 1;

  auto load_chunk = [&](int ci, uint32_t st){
    const int k0 = ci * 64;
    #pragma unroll
    for (int i = 0; i < 8; ++i){
      int id = i*256 + tid;
      int buf = id >> 10;
      int rem = id & 1023;
      int row = rem >> 3, seg = rem & 7;
      const __half* base = buf ? Bh : Ah;
      cpa16(sb + st + buf*16384 + SWADDR(row, seg), base + (size_t)row*Cc + k0 + seg*8);
    }
    CP_COMMIT();
  };

  load_chunk(0, 0);

  for (int ci = 0; ci < 6; ++ci){
    const uint32_t st = (ci & 1) * 32768;
    if (ci < 5) load_chunk(ci + 1, ((ci + 1) & 1) * 32768);
    if (ci < 5) { CP_WAIT1(); } else { CP_WAIT0(); }
    __syncthreads();

    #pragma unroll
    for (int kk = 0; kk < 4; ++kk){
      uint32_t ahf[2][4], bfr[4][4];
      #pragma unroll
      for (int mi = 0; mi < 2; ++mi)
        ldmx4(ahf[mi], SADDR(sb + st, m0w + mi*16 + arow, 2*kk + aseg));
      #pragma unroll
      for (int tp = 0; tp < 4; ++tp)
        ldmx4(bfr[tp], SADDR(sb + st + 16384, n0w + tp*16 + brow, 2*kk + bseg));
      #pragma unroll
      for (int tp = 0; tp < 4; ++tp){
        mmahf(acc[0][2*tp  ], ahf[0], bfr[tp][0], bfr[tp][1]);
        mmahf(acc[0][2*tp+1], ahf[0], bfr[tp][2], bfr[tp][3]);
        mmahf(acc[1][2*tp  ], ahf[1], bfr[tp][0], bfr[tp][1]);
        mmahf(acc[1][2*tp+1], ahf[1], bfr[tp][2], bfr[tp][3]);
      }
    }
    __syncthreads();
  }

  const int ddb = (l & 3) * 2;
  if (MODE == 0){
    const int t = m0blk / Cc;
    const float sc = (t == 0) ? QSC : 1.f;
    __half* dst = (t == 0) ? g_qh : (t == 1) ? g_kh : g_vh;
    #pragma unroll
    for (int mi = 0; mi < 2; ++mi){
      const int r0 = nsblk + m0w + mi*16 + (l >> 2);
      #pragma unroll
      for (int j = 0; j < 8; ++j){
        const int o = m0blk + n0w + j*8 + ddb;
        const int rem = o - t*Cc;
        const int hh = rem / HD, dd = rem % HD;
        float2 bv = *(const float2*)(bias + o);
        float v0 = (acc[mi][j][0] + bv.x) * sc;
        float v1 = (acc[mi][j][1] + bv.y) * sc;
        float v2 = (acc[mi][j][2] + bv.x) * sc;
        float v3 = (acc[mi][j][3] + bv.y) * sc;
        const int i0 = ((b*NH + hh)*Np + r0    )*HD + dd;
        const int i1 = ((b*NH + hh)*Np + r0 + 8)*HD + dd;
        *(uint32_t*)(dst + i0) = packhf(v0, v1);
        *(uint32_t*)(dst + i1) = packhf(v2, v3);
      }
    }
  } else {
    #pragma unroll
    for (int mi = 0; mi < 2; ++mi){
      const int or0 = m0blk + m0w + mi*16 + (l >> 2);
      const float b0 = __ldg(bias + or0), b1 = __ldg(bias + or0 + 8);
      #pragma unroll
      for (int j = 0; j < 8; ++j){
        const int nc = nsblk + n0w + j*8 + ddb;
        float2 s0 = make_float2(acc[mi][j][0] + b0, acc[mi][j][1] + b0);
        float2 s1 = make_float2(acc[mi][j][2] + b1, acc[mi][j][3] + b1);
        *(float2*)(outp + ((size_t)b*Cc + or0    )*Np + nc) = s0;
        *(float2*)(outp + ((size_t)b*Cc + or0 + 8)*Np + nc) = s1;
      }
    }
  }
}

// ------------------ attention (16q/warp, ones-MMA row-sum) ------------------
// smem: Qh@0 (16K); stage s @ 16384 + s*32768: Kh@0 Vh@16K  (80KB total)
__global__ __launch_bounds__(256, 2)
void attn_mma(int bh0)
{
  extern __shared__ char sm[];
  const uint32_t sb = smem_u32(sm);
  const int tid = threadIdx.x, wid = tid >> 5, l = tid & 31;
  const int bh = blockIdx.x + bh0;
  const int q0 = blockIdx.y * 128;

  const __half* kbh = g_kh + (size_t)bh*Np*HD;
  const __half* vbh = g_vh + (size_t)bh*Np*HD;

  auto load_kv = [&](int ch, uint32_t st){
    const int ko = ch * 128;
    #pragma unroll
    for (int i = 0; i < 6; ++i){
      int id = i*256 + tid;              // 0..1535
      int region = id >= 768;            // 0:Kh 1:Vh
      int rem = id - region*768;
      int row = rem / 6, seg = rem % 6;
      const __half* src = (region ? vbh : kbh) + (size_t)(ko + row)*HD + seg*8;
      cpa16(sb + st + region*16384 + SWADDR(row, seg), src);
    }
    CP_COMMIT();
  };

  // --- prologue: Q, then chunk-0 ---
  {
    const __half* qsh = g_qh + (size_t)(bh*Np + q0)*HD;
    #pragma unroll
    for (int i = 0; i < 3; ++i){
      int id = i*256 + tid;              // 0..767
      int row = id / 6, seg = id % 6;
      cpa16(sb + SWADDR(row, seg), qsh + row*HD + seg*8);
    }
    CP_COMMIT();
  }
  load_kv(0, 16384);
  CP_WAIT1();              // Q complete
  __syncthreads();

  const int m0w = wid * 16;
  const int arow = (l & 7) + ((l >> 3) & 1) * 8;
  const int aseg = (l >> 4);
  uint32_t qfh[3][4];
  #pragma unroll
  for (int ks = 0; ks < 3; ++ks)
    ldmx4(qfh[ks], SADDR(sb, m0w + arow, 2*ks + aseg));

  float oacc[6][4];
  #pragma unroll
  for (int j = 0; j < 6; ++j)
    #pragma unroll
    for (int e = 0; e < 4; ++e) oacc[j][e] = 0.f;
  float rsacc[4] = {0.f, 0.f, 0.f, 0.f};
  const uint32_t ONES = 0x3C003C00u;

  const int brow = (l & 7) + ((l >> 4) << 3);
  const int bseg = (l >> 3) & 1;
  const int vrow = (l & 7) + ((l >> 3) & 1) * 8;
  const int vsegb = (l >> 4);

  for (int ch = 0; ch < 8; ++ch){
    const uint32_t st = 16384 + (ch & 1) * 32768;
    if (ch < 7) load_kv(ch + 1, 16384 + ((ch + 1) & 1) * 32768);
    if (ch < 7) { CP_WAIT1(); } else { CP_WAIT0(); }
    __syncthreads();

    #pragma unroll
    for (int half = 0; half < 2; ++half){
      float sacc[8][4];
      #pragma unroll
      for (int j = 0; j < 8; ++j)
        #pragma unroll
        for (int e = 0; e < 4; ++e) sacc[j][e] = 0.f;

      #pragma unroll
      for (int ks = 0; ks < 3; ++ks){
        uint32_t bfr[4][4];
        #pragma unroll
        for (int tp = 0; tp < 4; ++tp)
          ldmx4(bfr[tp], SADDR(sb + st, half*64 + tp*16 + brow, 2*ks + bseg));
        #pragma unroll
        for (int tp = 0; tp < 4; ++tp){
          mmahf(sacc[2*tp  ], qfh[ks], bfr[tp][0], bfr[tp][1]);
          mmahf(sacc[2*tp+1], qfh[ks], bfr[tp][2], bfr[tp][3]);
        }
      }

      #pragma unroll
      for (int kt = 0; kt < 4; ++kt){
        float p0 = ex2(sacc[2*kt][0]),   p1 = ex2(sacc[2*kt][1]);
        float p2 = ex2(sacc[2*kt][2]),   p3 = ex2(sacc[2*kt][3]);
        float p4 = ex2(sacc[2*kt+1][0]), p5 = ex2(sacc[2*kt+1][1]);
        float p6 = ex2(sacc[2*kt+1][2]), p7 = ex2(sacc[2*kt+1][3]);
        uint32_t a[4];
        a[0] = packhf(p0, p1);  a[1] = packhf(p2, p3);
        a[2] = packhf(p4, p5);  a[3] = packhf(p6, p7);
        mmahf(rsacc, a, ONES, ONES);
        #pragma unroll
        for (int jp = 0; jp < 3; ++jp){
          uint32_t vh4[4];
          const int vr = half*64 + kt*16 + vrow;
          ldmx4t(vh4, SADDR(sb + st + 16384, vr, 2*jp + vsegb));
          mmahf(oacc[2*jp  ], a, vh4[0], vh4[1]);
          mmahf(oacc[2*jp+1], a, vh4[2], vh4[3]);
        }
      }
    }
    __syncthreads();
  }

  const float inv0 = 1.f / rsacc[0], inv1 = 1.f / rsacc[2];

  const int b = bh >> 3, h = bh & 7;
  const int row0 = q0 + m0w + (l >> 2);
  const int ddb = h*HD + (l & 3)*2;
  #pragma unroll
  for (int jd = 0; jd < 6; ++jd){
    const int i0 = ((b*Np + row0    )*Cc) + ddb + jd*8;
    const int i1 = ((b*Np + row0 + 8)*Cc) + ddb + jd*8;
    *(uint32_t*)(g_aoh + i0) = packhf(oacc[jd][0]*inv0, oacc[jd][1]*inv0);
    *(uint32_t*)(g_aoh + i1) = packhf(oacc[jd][2]*inv1, oacc[jd][3]*inv1);
  }
}

// ------------------ launch: two-stream batch-split pipeline (champion) ------------------
extern "C" void kernel_launch(void* const* d_in, const int* in_sizes, int n_in,
                              void* d_out, int out_size)
{
  const float* x      = (const float*)d_in[0];
  const float* w_qkv  = (const float*)d_in[1];
  const float* b_qkv  = (const float*)d_in[2];
  const float* w_proj = (const float*)d_in[3];
  const float* b_proj = (const float*)d_in[4];
  float* out = (float*)d_out;

  cudaFuncSetAttribute(gemm_mma<0>, cudaFuncAttributeMaxDynamicSharedMemorySize, 65536);
  cudaFuncSetAttribute(gemm_mma<1>, cudaFuncAttributeMaxDynamicSharedMemorySize, 65536);
  cudaFuncSetAttribute(attn_mma,    cudaFuncAttributeMaxDynamicSharedMemorySize, 81920);

  // second stream + fork/join events
  cudaStream_t s2;
  cudaStreamCreateWithFlags(&s2, cudaStreamNonBlocking);
  cudaEvent_t evF, evJ;
  cudaEventCreateWithFlags(&evF, cudaEventDisableTiming);
  cudaEventCreateWithFlags(&evJ, cudaEventDisableTiming);

  // shared prologue on the capture (default) stream
  wprep<<<dim3((3*Cc*Cc/2 + 255)/256, 2), 256>>>(w_qkv, w_proj);
  cudaEventRecord(evF, 0);
  cudaStreamWaitEvent(s2, evF, 0);

  // half 1: batches 0-3 on default stream
  xprep<<<dim3(32, 12, 4), 256>>>(x, 0);
  gemm_mma<0><<<dim3(8, 9, 4), 256, 65536>>>(b_qkv, nullptr, 0);
  attn_mma<<<dim3(32, 8), 256, 81920>>>(0);
  gemm_mma<1><<<dim3(8, 3, 4), 256, 65536>>>(b_proj, out, 0);

  // half 2: batches 4-7 on s2
  xprep<<<dim3(32, 12, 4), 256, 0, s2>>>(x, 4);
  gemm_mma<0><<<dim3(8, 9, 4), 256, 65536, s2>>>(b_qkv, nullptr, 4);
  attn_mma<<<dim3(32, 8), 256, 81920, s2>>>(32);
  gemm_mma<1><<<dim3(8, 3, 4), 256, 65536, s2>>>(b_proj, out, 4);
  cudaEventRecord(evJ, s2);
  cudaStreamWaitEvent(0, evJ, 0);

  cudaStreamDestroy(s2);
  cudaEventDestroy(evF);
  cudaEventDestroy(evJ);
}

// round 17
// speedup vs baseline: 1.0605x; 1.0159x over previous
#include <cuda_runtime.h>
#include <cuda_fp16.h>
#include <cstdint>
#include <math.h>

#define Bsz 8
#define Cc  384
#define Np  1024
#define NH  8
#define HD  48
#define SCALE 0.14433756729740643f
#define QSC  0.20824597962350385f   // SCALE * log2(e)

// ------------------ scratch (fp16 hi-only) ------------------
__device__ __align__(16) __half g_xTh[Bsz*Np*Cc];     // [b][n][c]
__device__ __align__(16) __half g_wqh[3*Cc*Cc];        // [o][c]
__device__ __align__(16) __half g_wph[Cc*Cc];          // [o][c]
__device__ __align__(16) __half g_qh[Bsz*NH*Np*HD];    // scaled by QSC
__device__ __align__(16) __half g_kh[Bsz*NH*Np*HD];
__device__ __align__(16) __half g_vh[Bsz*NH*Np*HD];
__device__ __align__(16) __half g_aoh[Bsz*Np*Cc];

// ------------------ helpers ------------------
__device__ __forceinline__ uint32_t smem_u32(const void* p){
  uint32_t a; asm("{ .reg .u64 t; cvta.to.shared.u64 t, %1; cvt.u32.u64 %0, t; }"
                  : "=r"(a) : "l"(p)); return a;
}
__device__ __forceinline__ void ldmx4(uint32_t* r, uint32_t a){
  asm volatile("ldmatrix.sync.aligned.m8n8.x4.shared.b16 {%0,%1,%2,%3}, [%4];"
    : "=r"(r[0]),"=r"(r[1]),"=r"(r[2]),"=r"(r[3]) : "r"(a));
}
__device__ __forceinline__ void ldmx4t(uint32_t* r, uint32_t a){
  asm volatile("ldmatrix.sync.aligned.m8n8.x4.trans.shared.b16 {%0,%1,%2,%3}, [%4];"
    : "=r"(r[0]),"=r"(r[1]),"=r"(r[2]),"=r"(r[3]) : "r"(a));
}
__device__ __forceinline__ void mmahf(float* c, const uint32_t* a, uint32_t b0, uint32_t b1){
  asm volatile("mma.sync.aligned.m16n8k16.row.col.f32.f16.f16.f32 "
    "{%0,%1,%2,%3},{%4,%5,%6,%7},{%8,%9},{%0,%1,%2,%3};"
    : "+f"(c[0]),"+f"(c[1]),"+f"(c[2]),"+f"(c[3])
    : "r"(a[0]),"r"(a[1]),"r"(a[2]),"r"(a[3]),"r"(b0),"r"(b1));
}
__device__ __forceinline__ uint32_t packhf(float x, float y){
  __half2 h = __floats2half2_rn(x, y);
  return *(uint32_t*)&h;
}
__device__ __forceinline__ float ex2(float x){
  float r; asm("ex2.approx.f32 %0, %1;" : "=f"(r) : "f"(x)); return r;
}
__device__ __forceinline__ void cpa16(uint32_t d, const void* s){
  asm volatile("cp.async.cg.shared.global [%0], [%1], 16;" :: "r"(d), "l"(s));
}
#define CP_COMMIT() asm volatile("cp.async.commit_group;" ::: "memory")
#define CP_WAIT0()  asm volatile("cp.async.wait_group 0;" ::: "memory")
#define CP_WAIT1()  asm volatile("cp.async.wait_group 1;" ::: "memory")
__device__ __forceinline__ uint32_t SADDR(uint32_t base, int row, int seg){
  return base + (row << 7) + (((seg ^ (row & 7)) & 7) << 4);
}
__device__ __forceinline__ uint32_t SWADDR(int row, int seg){
  return (row << 7) + (((seg ^ (row & 7)) & 7) << 4);
}

// ------------------ prep kernels ------------------
__global__ __launch_bounds__(256)
void xprep(const float* __restrict__ x, int b0){
  __shared__ float t[32][33];
  const int b = blockIdx.z + b0, n0 = blockIdx.x*32, c0 = blockIdx.y*32;
  const int lx = threadIdx.x & 31, ly = threadIdx.x >> 5;
  const float* xb = x + ((size_t)b*Cc + c0)*Np + n0;
  #pragma unroll
  for (int j = 0; j < 4; ++j)
    t[ly + j*8][lx] = xb[(size_t)(ly + j*8)*Np + lx];
  __syncthreads();
  const int r = threadIdx.x >> 4, cp = threadIdx.x & 15;
  #pragma unroll
  for (int j = 0; j < 2; ++j){
    int rr = r + j*16;
    int idx = ((b*Np + n0 + rr)*Cc + c0 + cp*2);
    *(uint32_t*)(g_xTh + idx) = packhf(t[cp*2][rr], t[cp*2+1][rr]);
  }
}

__global__ __launch_bounds__(256)
void wprep(const float* __restrict__ wq, const float* __restrict__ wp){
  const int i = blockIdx.x*256 + threadIdx.x;
  if (blockIdx.y == 0){
    if (i < 3*Cc*Cc/2){
      float2 v = *(const float2*)(wq + (size_t)i*2);
      ((uint32_t*)g_wqh)[i] = packhf(v.x, v.y);
    }
  } else {
    if (i < Cc*Cc/2){
      float2 v = *(const float2*)(wp + (size_t)i*2);
      ((uint32_t*)g_wph)[i] = packhf(v.x, v.y);
    }
  }
}

// ------------------ GEMM (fp16 single-pass, 3-stage cp.async pipeline, 1 sync/chunk) ------------------
// smem: stage s @ (s%3)*32768: A@0 B@16K   (96KB total)
template<int MODE>
__global__ __launch_bounds__(256, 2)
void gemm_mma(const float* __restrict__ bias, float* __restrict__ outp, int bofs)
{
  extern __shared__ char sm[];
  const uint32_t sb = smem_u32(sm);
  const int tid = threadIdx.x, wid = tid >> 5, l = tid & 31;
  const int b = blockIdx.z + bofs;
  const int m0blk = blockIdx.y * 128;
  const int nsblk = blockIdx.x * 128;

  const __half *Ah, *Bh;
  if (MODE == 0){
    Ah = g_xTh + (size_t)(b*Np + nsblk)*Cc;
    Bh = g_wqh + (size_t)m0blk*Cc;
  } else {
    Ah = g_wph + (size_t)m0blk*Cc;
    Bh = g_aoh + (size_t)(b*Np + nsblk)*Cc;
  }

  float acc[2][8][4];
  #pragma unroll
  for (int i = 0; i < 2; ++i)
    #pragma unroll
    for (int j = 0; j < 8; ++j)
      #pragma unroll
      for (int e = 0; e < 4; ++e) acc[i][j][e] = 0.f;

  const int m0w = (wid >> 1) * 32;
  const int n0w = (wid & 1) * 64;
  const int arow = (l & 7) + ((l >> 3) & 1) * 8;
  const int aseg = (l >> 4);
  const int brow = (l & 7) + ((l >> 4) << 3);
  const int bseg = (l >> 3) & 1;

  auto load_chunk = [&](int ci, uint32_t st){
    const int k0 = ci * 64;
    #pragma unroll
    for (int i = 0; i < 8; ++i){
      int id = i*256 + tid;
      int buf = id >> 10;
      int rem = id & 1023;
      int row = rem >> 3, seg = rem & 7;
      const __half* base = buf ? Bh : Ah;
      cpa16(sb + st + buf*16384 + SWADDR(row, seg), base + (size_t)row*Cc + k0 + seg*8);
    }
    CP_COMMIT();
  };

  load_chunk(0, 0);
  load_chunk(1, 32768);

  for (int ci = 0; ci < 6; ++ci){
    const uint32_t st = (uint32_t)(ci % 3) * 32768;
    if (ci < 5) { CP_WAIT1(); } else { CP_WAIT0(); }
    __syncthreads();

    #pragma unroll
    for (int kk = 0; kk < 4; ++kk){
      uint32_t ahf[2][4], bfr[4][4];
      #pragma unroll
      for (int mi = 0; mi < 2; ++mi)
        ldmx4(ahf[mi], SADDR(sb + st, m0w + mi*16 + arow, 2*kk + aseg));
      #pragma unroll
      for (int tp = 0; tp < 4; ++tp)
        ldmx4(bfr[tp], SADDR(sb + st + 16384, n0w + tp*16 + brow, 2*kk + bseg));
      #pragma unroll
      for (int tp = 0; tp < 4; ++tp){
        mmahf(acc[0][2*tp  ], ahf[0], bfr[tp][0], bfr[tp][1]);
        mmahf(acc[0][2*tp+1], ahf[0], bfr[tp][2], bfr[tp][3]);
        mmahf(acc[1][2*tp  ], ahf[1], bfr[tp][0], bfr[tp][1]);
        mmahf(acc[1][2*tp+1], ahf[1], bfr[tp][2], bfr[tp][3]);
      }
    }
    // issue next-next chunk; stage (ci+2)%3 == (ci-1)%3 was read at compute(ci-1),
    // and sync(ci) above guarantees all warps finished compute(ci-1).
    if (ci + 2 < 6) load_chunk(ci + 2, (uint32_t)((ci + 2) % 3) * 32768);
  }

  const int ddb = (l & 3) * 2;
  if (MODE == 0){
    const int t = m0blk / Cc;
    const float sc = (t == 0) ? QSC : 1.f;
    __half* dst = (t == 0) ? g_qh : (t == 1) ? g_kh : g_vh;
    #pragma unroll
    for (int mi = 0; mi < 2; ++mi){
      const int r0 = nsblk + m0w + mi*16 + (l >> 2);
      #pragma unroll
      for (int j = 0; j < 8; ++j){
        const int o = m0blk + n0w + j*8 + ddb;
        const int rem = o - t*Cc;
        const int hh = rem / HD, dd = rem % HD;
        float2 bv = *(const float2*)(bias + o);
        float v0 = (acc[mi][j][0] + bv.x) * sc;
        float v1 = (acc[mi][j][1] + bv.y) * sc;
        float v2 = (acc[mi][j][2] + bv.x) * sc;
        float v3 = (acc[mi][j][3] + bv.y) * sc;
        const int i0 = ((b*NH + hh)*Np + r0    )*HD + dd;
        const int i1 = ((b*NH + hh)*Np + r0 + 8)*HD + dd;
        *(uint32_t*)(dst + i0) = packhf(v0, v1);
        *(uint32_t*)(dst + i1) = packhf(v2, v3);
      }
    }
  } else {
    #pragma unroll
    for (int mi = 0; mi < 2; ++mi){
      const int or0 = m0blk + m0w + mi*16 + (l >> 2);
      const float b0 = __ldg(bias + or0), b1 = __ldg(bias + or0 + 8);
      #pragma unroll
      for (int j = 0; j < 8; ++j){
        const int nc = nsblk + n0w + j*8 + ddb;
        float2 s0 = make_float2(acc[mi][j][0] + b0, acc[mi][j][1] + b0);
        float2 s1 = make_float2(acc[mi][j][2] + b1, acc[mi][j][3] + b1);
        *(float2*)(outp + ((size_t)b*Cc + or0    )*Np + nc) = s0;
        *(float2*)(outp + ((size_t)b*Cc + or0 + 8)*Np + nc) = s1;
      }
    }
  }
}

// ------------------ attention (16q/warp, ones-MMA row-sum, 3-stage pipeline) ------------------
// smem: Qh@0 (16K); stage s @ 16384 + (s%3)*32768: Kh@0 Vh@16K  (112KB total)
__global__ __launch_bounds__(256, 2)
void attn_mma(int bh0)
{
  extern __shared__ char sm[];
  const uint32_t sb = smem_u32(sm);
  const int tid = threadIdx.x, wid = tid >> 5, l = tid & 31;
  const int bh = blockIdx.x + bh0;
  const int q0 = blockIdx.y * 128;

  const __half* kbh = g_kh + (size_t)bh*Np*HD;
  const __half* vbh = g_vh + (size_t)bh*Np*HD;

  auto load_kv = [&](int ch, uint32_t st){
    const int ko = ch * 128;
    #pragma unroll
    for (int i = 0; i < 6; ++i){
      int id = i*256 + tid;              // 0..1535
      int region = id >= 768;            // 0:Kh 1:Vh
      int rem = id - region*768;
      int row = rem / 6, seg = rem % 6;
      const __half* src = (region ? vbh : kbh) + (size_t)(ko + row)*HD + seg*8;
      cpa16(sb + st + region*16384 + SWADDR(row, seg), src);
    }
    CP_COMMIT();
  };

  // --- prologue: Q, kv0, kv1 ---
  {
    const __half* qsh = g_qh + (size_t)(bh*Np + q0)*HD;
    #pragma unroll
    for (int i = 0; i < 3; ++i){
      int id = i*256 + tid;              // 0..767
      int row = id / 6, seg = id % 6;
      cpa16(sb + SWADDR(row, seg), qsh + row*HD + seg*8);
    }
    CP_COMMIT();
  }
  load_kv(0, 16384);
  load_kv(1, 16384 + 32768);
  CP_WAIT1();              // Q + kv0 complete (kv1 may pend)
  __syncthreads();

  const int m0w = wid * 16;
  const int arow = (l & 7) + ((l >> 3) & 1) * 8;
  const int aseg = (l >> 4);
  uint32_t qfh[3][4];
  #pragma unroll
  for (int ks = 0; ks < 3; ++ks)
    ldmx4(qfh[ks], SADDR(sb, m0w + arow, 2*ks + aseg));

  float oacc[6][4];
  #pragma unroll
  for (int j = 0; j < 6; ++j)
    #pragma unroll
    for (int e = 0; e < 4; ++e) oacc[j][e] = 0.f;
  float rsacc[4] = {0.f, 0.f, 0.f, 0.f};
  const uint32_t ONES = 0x3C003C00u;

  const int brow = (l & 7) + ((l >> 4) << 3);
  const int bseg = (l >> 3) & 1;
  const int vrow = (l & 7) + ((l >> 3) & 1) * 8;
  const int vsegb = (l >> 4);

  for (int ch = 0; ch < 8; ++ch){
    const uint32_t st = 16384 + (uint32_t)(ch % 3) * 32768;
    if (ch >= 1){
      if (ch < 7) { CP_WAIT1(); } else { CP_WAIT0(); }
      __syncthreads();
    }

    #pragma unroll
    for (int half = 0; half < 2; ++half){
      float sacc[8][4];
      #pragma unroll
      for (int j = 0; j < 8; ++j)
        #pragma unroll
        for (int e = 0; e < 4; ++e) sacc[j][e] = 0.f;

      #pragma unroll
      for (int ks = 0; ks < 3; ++ks){
        uint32_t bfr[4][4];
        #pragma unroll
        for (int tp = 0; tp < 4; ++tp)
          ldmx4(bfr[tp], SADDR(sb + st, half*64 + tp*16 + brow, 2*ks + bseg));
        #pragma unroll
        for (int tp = 0; tp < 4; ++tp){
          mmahf(sacc[2*tp  ], qfh[ks], bfr[tp][0], bfr[tp][1]);
          mmahf(sacc[2*tp+1], qfh[ks], bfr[tp][2], bfr[tp][3]);
        }
      }

      #pragma unroll
      for (int kt = 0; kt < 4; ++kt){
        float p0 = ex2(sacc[2*kt][0]),   p1 = ex2(sacc[2*kt][1]);
        float p2 = ex2(sacc[2*kt][2]),   p3 = ex2(sacc[2*kt][3]);
        float p4 = ex2(sacc[2*kt+1][0]), p5 = ex2(sacc[2*kt+1][1]);
        float p6 = ex2(sacc[2*kt+1][2]), p7 = ex2(sacc[2*kt+1][3]);
        uint32_t a[4];
        a[0] = packhf(p0, p1);  a[1] = packhf(p2, p3);
        a[2] = packhf(p4, p5);  a[3] = packhf(p6, p7);
        mmahf(rsacc, a, ONES, ONES);
        #pragma unroll
        for (int jp = 0; jp < 3; ++jp){
          uint32_t vh4[4];
          const int vr = half*64 + kt*16 + vrow;
          ldmx4t(vh4, SADDR(sb + st + 16384, vr, 2*jp + vsegb));
          mmahf(oacc[2*jp  ], a, vh4[0], vh4[1]);
          mmahf(oacc[2*jp+1], a, vh4[2], vh4[3]);
        }
      }
    }
    // issue next-next chunk; stage (ch+2)%3 == (ch-1)%3 was read at compute(ch-1),
    // and sync(ch) above guarantees all warps finished compute(ch-1).
    if (ch + 2 <= 7) load_kv(ch + 2, 16384 + (uint32_t)((ch + 2) % 3) * 32768);
  }

  const float inv0 = 1.f / rsacc[0], inv1 = 1.f / rsacc[2];

  const int b = bh >> 3, h = bh & 7;
  const int row0 = q0 + m0w + (l >> 2);
  const int ddb = h*HD + (l & 3)*2;
  #pragma unroll
  for (int jd = 0; jd < 6; ++jd){
    const int i0 = ((b*Np + row0    )*Cc) + ddb + jd*8;
    const int i1 = ((b*Np + row0 + 8)*Cc) + ddb + jd*8;
    *(uint32_t*)(g_aoh + i0) = packhf(oacc[jd][0]*inv0, oacc[jd][1]*inv0);
    *(uint32_t*)(g_aoh + i1) = packhf(oacc[jd][2]*inv1, oacc[jd][3]*inv1);
  }
}

// ------------------ launch: two-stream batch-split pipeline ------------------
extern "C" void kernel_launch(void* const* d_in, const int* in_sizes, int n_in,
                              void* d_out, int out_size)
{
  const float* x      = (const float*)d_in[0];
  const float* w_qkv  = (const float*)d_in[1];
  const float* b_qkv  = (const float*)d_in[2];
  const float* w_proj = (const float*)d_in[3];
  const float* b_proj = (const float*)d_in[4];
  float* out = (float*)d_out;

  cudaFuncSetAttribute(gemm_mma<0>, cudaFuncAttributeMaxDynamicSharedMemorySize, 98304);
  cudaFuncSetAttribute(gemm_mma<1>, cudaFuncAttributeMaxDynamicSharedMemorySize, 98304);
  cudaFuncSetAttribute(attn_mma,    cudaFuncAttributeMaxDynamicSharedMemorySize, 114688);

  // second stream + fork/join events
  cudaStream_t s2;
  cudaStreamCreateWithFlags(&s2, cudaStreamNonBlocking);
  cudaEvent_t evF, evJ;
  cudaEventCreateWithFlags(&evF, cudaEventDisableTiming);
  cudaEventCreateWithFlags(&evJ, cudaEventDisableTiming);

  // shared prologue on the capture (default) stream
  wprep<<<dim3((3*Cc*Cc/2 + 255)/256, 2), 256>>>(w_qkv, w_proj);
  cudaEventRecord(evF, 0);
  cudaStreamWaitEvent(s2, evF, 0);

  // half 1: batches 0-3 on default stream
  xprep<<<dim3(32, 12, 4), 256>>>(x, 0);
  gemm_mma<0><<<dim3(8, 9, 4), 256, 98304>>>(b_qkv, nullptr, 0);
  attn_mma<<<dim3(32, 8), 256, 114688>>>(0);
  gemm_mma<1><<<dim3(8, 3, 4), 256, 98304>>>(b_proj, out, 0);

  // half 2: batches 4-7 on s2
  xprep<<<dim3(32, 12, 4), 256, 0, s2>>>(x, 4);
  gemm_mma<0><<<dim3(8, 9, 4), 256, 98304, s2>>>(b_qkv, nullptr, 4);
  attn_mma<<<dim3(32, 8), 256, 114688, s2>>>(32);
  gemm_mma<1><<<dim3(8, 3, 4), 256, 98304, s2>>>(b_proj, out, 4);
  cudaEventRecord(evJ, s2);
  cudaStreamWaitEvent(0, evJ, 0);

  cudaStreamDestroy(s2);
  cudaEventDestroy(evF);
  cudaEventDestroy(evJ);
}